// round 15
// baseline (speedup 1.0000x reference)
#include <cuda_runtime.h>
#include <cuda_fp16.h>
#include <math.h>
#include <stdint.h>

#define BB 16
#define NN 1024
#define DD 64
#define LOG2E 1.4426950408889634f
#define NPART 32            /* column partials per batch */

// ---------------- scratch (static device globals; no allocations) ----------
__device__ float g_C[BB * NN * NN];        // C2 = -C * inv_eps * LOG2E  (<= 0)
__device__ float g_part[BB * NPART * NN];  // column partials (2 MB)
__device__ float g_x2[BB * NN];
__device__ float g_y2[BB * NN];
__device__ float g_Lu2[BB * NN];           // (log_u + cmin/eps) * LOG2E
__device__ float g_Lv2[BB * NN];           // (log_v + cmin/eps) * LOG2E
__device__ unsigned int g_cminbits[BB];
__device__ float g_inv_eps;

// ---------------- helpers ---------------------------------------------------
__device__ __forceinline__ float ex2(float x) {
    float r;
    asm("ex2.approx.ftz.f32 %0, %1;" : "=f"(r) : "f"(x));
    return r;
}
__device__ __forceinline__ float lg2(float x) {
    float r;
    asm("lg2.approx.f32 %0, %1;" : "=f"(r) : "f"(x));
    return r;
}

__device__ __forceinline__ unsigned h2_as_u32(__half2 h) {
    unsigned u;
    memcpy(&u, &h, 4);
    return u;
}
__device__ __forceinline__ __half2 u32_as_h2(unsigned u) {
    __half2 h;
    memcpy(&h, &u, 4);
    return h;
}

__device__ __forceinline__ float read_eps(const void* p) {
    float f = *(const float*)p;
    if (isfinite(f) && fabsf(f) > 1e-20f && fabsf(f) < 1e20f) return f;
    return (float)(*(const int*)p);
}

// ---------------- prep: x2, y2, eps, cmin init ------------------------------
__global__ void k_prep(const float* __restrict__ x, const float* __restrict__ y,
                       const void* __restrict__ epsp) {
    int idx = blockIdx.x * blockDim.x + threadIdx.x;
    if (idx == 0) g_inv_eps = 1.0f / read_eps(epsp);
    if (idx < BB) g_cminbits[idx] = 0x7F800000u;  // +inf
    if (idx < BB * NN) {
        const float4* xr = (const float4*)(x + (size_t)idx * DD);
        float s = 0.0f;
#pragma unroll
        for (int j = 0; j < DD / 4; j++) {
            float4 v = xr[j];
            s += v.x * v.x + v.y * v.y + v.z * v.z + v.w * v.w;
        }
        g_x2[idx] = s;
    } else if (idx < 2 * BB * NN) {
        int j2 = idx - BB * NN;
        const float4* yr = (const float4*)(y + (size_t)j2 * DD);
        float s = 0.0f;
#pragma unroll
        for (int j = 0; j < DD / 4; j++) {
            float4 v = yr[j];
            s += v.x * v.x + v.y * v.y + v.z * v.z + v.w * v.w;
        }
        g_y2[j2] = s;
    }
}

// ---------------- C2 = -max(x2+y2-2x.y,0)*inv_eps*LOG2E; track raw min ------
__global__ void k_gemm(const float* __restrict__ x, const float* __restrict__ y) {
    __shared__ float xs[64][65];
    __shared__ float ys[64][65];
    __shared__ float wmin[8];

    const int b  = blockIdx.z;
    const int n0 = blockIdx.y * 64;
    const int m0 = blockIdx.x * 64;
    const int t  = threadIdx.x;

    {
        int row = t >> 4;
        int col = (t & 15) * 4;
#pragma unroll
        for (int rr = 0; rr < 4; rr++) {
            int r = row + 16 * rr;
            float4 vx = *(const float4*)(x + ((size_t)(b * NN + n0 + r)) * DD + col);
            xs[r][col + 0] = vx.x; xs[r][col + 1] = vx.y;
            xs[r][col + 2] = vx.z; xs[r][col + 3] = vx.w;
            float4 vy = *(const float4*)(y + ((size_t)(b * NN + m0 + r)) * DD + col);
            ys[r][col + 0] = vy.x; ys[r][col + 1] = vy.y;
            ys[r][col + 2] = vy.z; ys[r][col + 3] = vy.w;
        }
    }
    __syncthreads();

    const int tn = t >> 4;
    const int tm = t & 15;
    float acc[4][4];
#pragma unroll
    for (int i = 0; i < 4; i++)
#pragma unroll
        for (int j = 0; j < 4; j++) acc[i][j] = 0.0f;

#pragma unroll 8
    for (int k = 0; k < 64; k++) {
        float a[4], bb_[4];
#pragma unroll
        for (int i = 0; i < 4; i++) a[i] = xs[tn * 4 + i][k];
#pragma unroll
        for (int j = 0; j < 4; j++) bb_[j] = ys[tm * 4 + j][k];
#pragma unroll
        for (int i = 0; i < 4; i++)
#pragma unroll
            for (int j = 0; j < 4; j++) acc[i][j] += a[i] * bb_[j];
    }

    const float negScale = -g_inv_eps * LOG2E;
    float tmin = INFINITY;
#pragma unroll
    for (int i = 0; i < 4; i++) {
        int n = n0 + tn * 4 + i;
        float xx = g_x2[b * NN + n];
        float4 cv;
        float c[4];
#pragma unroll
        for (int j = 0; j < 4; j++) {
            int m = m0 + tm * 4 + j;
            float v = xx + g_y2[b * NN + m] - 2.0f * acc[i][j];
            v = fmaxf(v, 0.0f);
            tmin = fminf(tmin, v);
            c[j] = v * negScale;
        }
        cv.x = c[0]; cv.y = c[1]; cv.z = c[2]; cv.w = c[3];
        *(float4*)(g_C + ((size_t)(b * NN + n)) * NN + m0 + tm * 4) = cv;
    }

#pragma unroll
    for (int off = 16; off > 0; off >>= 1)
        tmin = fminf(tmin, __shfl_xor_sync(0xFFFFFFFFu, tmin, off));
    if ((t & 31) == 0) wmin[t >> 5] = tmin;
    __syncthreads();
    if (t == 0) {
        float bm = wmin[0];
#pragma unroll
        for (int w = 1; w < 8; w++) bm = fminf(bm, wmin[w]);
        atomicMin(&g_cminbits[b], __float_as_uint(bm));
    }
}

// ---------------- init Lu2/Lv2 = cmin*inv_eps*LOG2E (log_u = log_v = 0) -----
__global__ void k_init() {
    int idx = blockIdx.x * blockDim.x + threadIdx.x;
    if (idx < BB * NN) {
        int b = idx >> 10;
        float cminv2 = __uint_as_float(g_cminbits[b]) * g_inv_eps * LOG2E;
        g_Lu2[idx] = cminv2;
        g_Lv2[idx] = cminv2;
    }
}

// ---------------- initial column pass (run once): tile partial sums ----------
__global__ void __launch_bounds__(256) k_colP() {
    __shared__ float lus[32];
    __shared__ float4 part[16][16];   // [rowpart p][colgroup g]

    const int b    = blockIdx.z;
    const int m0   = blockIdx.x * 64;
    const int slab = blockIdx.y;
    const int n0   = slab * 32;
    const int t    = threadIdx.x;
    const int g    = t & 15;
    const int p    = t >> 4;

    if (t < 32) lus[t] = g_Lu2[b * NN + n0 + t];

    const float cminv2 = __uint_as_float(g_cminbits[b]) * g_inv_eps * LOG2E;
    const float Cv = cminv2 - 10.0f;   // - log2(1024)

    float4 pl = *(const float4*)(g_Lv2 + b * NN + m0 + 4 * g);
    float4 V0;
    V0.x = Cv - pl.x; V0.y = Cv - pl.y; V0.z = Cv - pl.z; V0.w = Cv - pl.w;
    __syncthreads();

    const float4* Cp = (const float4*)(g_C + ((size_t)(b * NN + n0)) * NN) + (m0 >> 2) + g;
    float s0 = 0.f, s1 = 0.f, s2 = 0.f, s3 = 0.f;
#pragma unroll
    for (int n = 2 * p; n < 2 * p + 2; n++) {
        float4 c = Cp[(size_t)n * (NN / 4)];
        float lu = lus[n];
        s0 += ex2(c.x + lu - V0.x);
        s1 += ex2(c.y + lu - V0.y);
        s2 += ex2(c.z + lu - V0.z);
        s3 += ex2(c.w + lu - V0.w);
    }
    part[p][g] = make_float4(s0, s1, s2, s3);
    __syncthreads();

    if (t < 64) {
        int gg = t >> 2, j = t & 3;
        float s = 0.0f;
#pragma unroll
        for (int q = 0; q < 16; q++) s += ((const float*)&part[q][gg])[j];
        g_part[((size_t)(b * NPART + slab)) * NN + m0 + t] = s;
    }
}

// ---------------- combine partials + log -> Lv2 ------------------------------
// grid (4, BB) x 256 threads; thread = one column; coalesced partial loads.
__global__ void __launch_bounds__(256) k_finv() {
    const int b = blockIdx.y;
    const int m = blockIdx.x * 256 + threadIdx.x;

    const float cminv2 = __uint_as_float(g_cminbits[b]) * g_inv_eps * LOG2E;
    const float Cv = cminv2 - 10.0f;

    const float* P = g_part + (size_t)b * NPART * NN + m;
    float s = 0.0f;
#pragma unroll
    for (int p = 0; p < NPART; p++) s += P[p * NN];

    float V = Cv - g_Lv2[b * NN + m];   // old V0 used by the partial pass
    float LSE2 = V + lg2(fmaxf(s, 1e-38f));
    g_Lv2[b * NN + m] = Cv - LSE2;
}

// ---------------- fused pass: u-update + column partials for next v ----------
// Block = 32 rows of one batch; 8 warps x 4 rows; warp owns the whole row,
// no intra-loop syncs. ONE read of C serves both updates:
//   e[m] = exp2(C2 + Lv[m] - V0r);  Lu_new = Cc - (V0r + log2(sum_m e));
//   column contribution = e[m] * exp2(Lu_new - Lu_old)   (exact identity).
// Since sum_m e[m]*An == 1 per row (u-normalization), every product is in
// (0,1] -> safe to accumulate in fp16 (halves accumulator registers ->
// 4 blocks/SM instead of 2).
__global__ void __launch_bounds__(256, 4) k_fused() {
    __shared__ float4 lv2s[NN / 4];       // 4 KB
    __shared__ uint2  swacc2[8][NN / 4];  // 16 KB per-warp half2-packed partials

    const int b    = blockIdx.y;
    const int t    = threadIdx.x;
    const int lane = t & 31;
    const int w    = t >> 5;
    const int r0   = blockIdx.x * 32 + w * 4;

    lv2s[t] = ((const float4*)(g_Lv2 + b * NN))[t];

    const float cminv2 = __uint_as_float(g_cminbits[b]) * g_inv_eps * LOG2E;
    const float Cc = cminv2 - 10.0f;
    __syncthreads();

    __half2 ca[16];
#pragma unroll
    for (int j = 0; j < 16; j++) ca[j] = __floats2half2_rn(0.f, 0.f);

#pragma unroll
    for (int rr = 0; rr < 4; rr++) {
        const int row = r0 + rr;
        const float Lu_old = g_Lu2[b * NN + row];
        const float V0 = Cc - Lu_old;
        const float4* Crow = (const float4*)(g_C + ((size_t)(b * NN + row)) * NN);

        float4 e[8];
        float s0 = 0.f, s1 = 0.f, s2 = 0.f, s3 = 0.f;
#pragma unroll
        for (int j = 0; j < 8; j++) {
            int i = lane + 32 * j;
            float4 c = Crow[i];
            float4 lv = lv2s[i];
            e[j].x = ex2(c.x + lv.x - V0);
            e[j].y = ex2(c.y + lv.y - V0);
            e[j].z = ex2(c.z + lv.z - V0);
            e[j].w = ex2(c.w + lv.w - V0);
            s0 += e[j].x; s1 += e[j].y; s2 += e[j].z; s3 += e[j].w;
        }
        float s = (s0 + s1) + (s2 + s3);
#pragma unroll
        for (int off = 16; off > 0; off >>= 1)
            s += __shfl_xor_sync(0xFFFFFFFFu, s, off);

        float LSE2 = V0 + lg2(fmaxf(s, 1e-38f));
        float Lu_new = Cc - LSE2;
        if (lane == 0) g_Lu2[b * NN + row] = Lu_new;

        float An = ex2(Lu_new - Lu_old);
#pragma unroll
        for (int j = 0; j < 8; j++) {
            ca[2 * j]     = __hadd2(ca[2 * j],
                                    __floats2half2_rn(e[j].x * An, e[j].y * An));
            ca[2 * j + 1] = __hadd2(ca[2 * j + 1],
                                    __floats2half2_rn(e[j].z * An, e[j].w * An));
        }
    }

    // dump per-warp packed accumulators (conflict-free STS.64)
#pragma unroll
    for (int j = 0; j < 8; j++) {
        uint2 u;
        u.x = h2_as_u32(ca[2 * j]);       // columns 4i, 4i+1
        u.y = h2_as_u32(ca[2 * j + 1]);   // columns 4i+2, 4i+3
        swacc2[w][lane + 32 * j] = u;
    }
    __syncthreads();

    // merge 8 warps in fp32: thread t covers columns 4t..4t+3
    {
        float2 a0 = make_float2(0.f, 0.f), a1 = make_float2(0.f, 0.f);
#pragma unroll
        for (int ww = 0; ww < 8; ww++) {
            uint2 u = swacc2[ww][t];
            float2 p0 = __half22float2(u32_as_h2(u.x));
            float2 p1 = __half22float2(u32_as_h2(u.y));
            a0.x += p0.x; a0.y += p0.y;
            a1.x += p1.x; a1.y += p1.y;
        }
        float4 r;
        r.x = a0.x; r.y = a0.y; r.z = a1.x; r.w = a1.y;
        ((float4*)(g_part + ((size_t)(b * NPART + blockIdx.x)) * NN))[t] = r;
    }
}

// ---------------- output -----------------------------------------------------
// w[n,m] = exp2(C2[n,m] + Lu2[n] + Lv2[m] - cminv2); out = (w @ y) / rowsum(w)
__global__ void k_out(const float* __restrict__ y, float* __restrict__ out) {
    __shared__ __align__(16) float ysm[64 * 64];
    __shared__ float wt[16 * 65];

    const int b  = blockIdx.y;
    const int n0 = blockIdx.x * 16;
    const int t  = threadIdx.x;
    const int r  = t >> 4;
    const int dg = t & 15;

    const float cminv2 = __uint_as_float(g_cminbits[b]) * g_inv_eps * LOG2E;

    float4 acc = make_float4(0.f, 0.f, 0.f, 0.f);
    float wsum = 0.0f;

    for (int mt = 0; mt < NN; mt += 64) {
#pragma unroll
        for (int r2 = 0; r2 < 4; r2++) {
            int fid = t + 256 * r2;
            int row = fid >> 4;
            int col4 = fid & 15;
            ((float4*)ysm)[fid] =
                *(const float4*)(y + ((size_t)(b * NN + mt + row)) * DD + col4 * 4);
        }
        {
            int wid = t * 4;
            int rw = wid >> 6;
            int mmw = wid & 63;
            float4 cv = *(const float4*)(g_C + ((size_t)(b * NN + n0 + rw)) * NN + mt + mmw);
            float4 lv = *(const float4*)(g_Lv2 + b * NN + mt + mmw);
            float lu = g_Lu2[b * NN + n0 + rw] - cminv2;
            wt[rw * 65 + mmw + 0] = ex2(cv.x + lv.x + lu);
            wt[rw * 65 + mmw + 1] = ex2(cv.y + lv.y + lu);
            wt[rw * 65 + mmw + 2] = ex2(cv.z + lv.z + lu);
            wt[rw * 65 + mmw + 3] = ex2(cv.w + lv.w + lu);
        }
        __syncthreads();

#pragma unroll 16
        for (int mm = 0; mm < 64; mm++) {
            float w = wt[r * 65 + mm];
            float4 yv = *(const float4*)(ysm + mm * 64 + dg * 4);
            acc.x += w * yv.x;
            acc.y += w * yv.y;
            acc.z += w * yv.z;
            acc.w += w * yv.w;
            wsum += w;
        }
        __syncthreads();
    }

    float rinv = 1.0f / fmaxf(wsum, 1e-12f);
    float4 o;
    o.x = acc.x * rinv; o.y = acc.y * rinv;
    o.z = acc.z * rinv; o.w = acc.w * rinv;
    *(float4*)(out + ((size_t)(b * NN + n0 + r)) * DD + dg * 4) = o;
}

// ---------------- launcher ---------------------------------------------------
extern "C" void kernel_launch(void* const* d_in, const int* in_sizes, int n_in,
                              void* d_out, int out_size) {
    const float* x = (const float*)d_in[0];
    const float* y = (const float*)d_in[1];
    const void* eps = d_in[2];
    float* out = (float*)d_out;

    k_prep<<<(2 * BB * NN + 255) / 256, 256>>>(x, y, eps);
    k_gemm<<<dim3(NN / 64, NN / 64, BB), 256>>>(x, y);
    k_init<<<(BB * NN + 255) / 256, 256>>>();

    // v-update #1 (uses Lu = init)
    k_colP<<<dim3(NN / 64, NPART, BB), 256>>>();
    k_finv<<<dim3(NN / 256, BB), 256>>>();

    // 50 x { u-update k ; column partials for v-update k+1 ; finish v-update }
    for (int it = 0; it < 50; it++) {
        k_fused<<<dim3(NN / 32, BB), 256>>>();
        k_finv<<<dim3(NN / 256, BB), 256>>>();
    }

    k_out<<<dim3(NN / 16, BB), 256>>>(y, out);
}

// round 17
// speedup vs baseline: 2.2801x; 2.2801x over previous
#include <cuda_runtime.h>
#include <math.h>
#include <stdint.h>

#define BB 16
#define NN 1024
#define DD 64
#define LOG2E 1.4426950408889634f
#define NPART 16            /* column partials per batch (= fused blocks/batch) */

// ---------------- scratch (static device globals; no allocations) ----------
__device__ float g_C[BB * NN * NN];        // C2 = -C * inv_eps * LOG2E  (<= 0)
__device__ float g_part[BB * NPART * NN];  // column partials (1 MB)
__device__ float g_x2[BB * NN];
__device__ float g_y2[BB * NN];
__device__ float g_Lu2[BB * NN];           // (log_u + cmin/eps) * LOG2E
__device__ float g_Lv2[BB * NN];           // (log_v + cmin/eps) * LOG2E
__device__ unsigned int g_cminbits[BB];
__device__ float g_inv_eps;

// ---------------- helpers ---------------------------------------------------
__device__ __forceinline__ float ex2(float x) {
    float r;
    asm("ex2.approx.ftz.f32 %0, %1;" : "=f"(r) : "f"(x));
    return r;
}
__device__ __forceinline__ float lg2(float x) {
    float r;
    asm("lg2.approx.f32 %0, %1;" : "=f"(r) : "f"(x));
    return r;
}

__device__ __forceinline__ float read_eps(const void* p) {
    float f = *(const float*)p;
    if (isfinite(f) && fabsf(f) > 1e-20f && fabsf(f) < 1e20f) return f;
    return (float)(*(const int*)p);
}

// ---------------- prep: x2, y2, eps, cmin init ------------------------------
__global__ void k_prep(const float* __restrict__ x, const float* __restrict__ y,
                       const void* __restrict__ epsp) {
    int idx = blockIdx.x * blockDim.x + threadIdx.x;
    if (idx == 0) g_inv_eps = 1.0f / read_eps(epsp);
    if (idx < BB) g_cminbits[idx] = 0x7F800000u;  // +inf
    if (idx < BB * NN) {
        const float4* xr = (const float4*)(x + (size_t)idx * DD);
        float s = 0.0f;
#pragma unroll
        for (int j = 0; j < DD / 4; j++) {
            float4 v = xr[j];
            s += v.x * v.x + v.y * v.y + v.z * v.z + v.w * v.w;
        }
        g_x2[idx] = s;
    } else if (idx < 2 * BB * NN) {
        int j2 = idx - BB * NN;
        const float4* yr = (const float4*)(y + (size_t)j2 * DD);
        float s = 0.0f;
#pragma unroll
        for (int j = 0; j < DD / 4; j++) {
            float4 v = yr[j];
            s += v.x * v.x + v.y * v.y + v.z * v.z + v.w * v.w;
        }
        g_y2[j2] = s;
    }
}

// ---------------- C2 = -max(x2+y2-2x.y,0)*inv_eps*LOG2E; track raw min ------
__global__ void k_gemm(const float* __restrict__ x, const float* __restrict__ y) {
    __shared__ float xs[64][65];
    __shared__ float ys[64][65];
    __shared__ float wmin[8];

    const int b  = blockIdx.z;
    const int n0 = blockIdx.y * 64;
    const int m0 = blockIdx.x * 64;
    const int t  = threadIdx.x;

    {
        int row = t >> 4;
        int col = (t & 15) * 4;
#pragma unroll
        for (int rr = 0; rr < 4; rr++) {
            int r = row + 16 * rr;
            float4 vx = *(const float4*)(x + ((size_t)(b * NN + n0 + r)) * DD + col);
            xs[r][col + 0] = vx.x; xs[r][col + 1] = vx.y;
            xs[r][col + 2] = vx.z; xs[r][col + 3] = vx.w;
            float4 vy = *(const float4*)(y + ((size_t)(b * NN + m0 + r)) * DD + col);
            ys[r][col + 0] = vy.x; ys[r][col + 1] = vy.y;
            ys[r][col + 2] = vy.z; ys[r][col + 3] = vy.w;
        }
    }
    __syncthreads();

    const int tn = t >> 4;
    const int tm = t & 15;
    float acc[4][4];
#pragma unroll
    for (int i = 0; i < 4; i++)
#pragma unroll
        for (int j = 0; j < 4; j++) acc[i][j] = 0.0f;

#pragma unroll 8
    for (int k = 0; k < 64; k++) {
        float a[4], bb_[4];
#pragma unroll
        for (int i = 0; i < 4; i++) a[i] = xs[tn * 4 + i][k];
#pragma unroll
        for (int j = 0; j < 4; j++) bb_[j] = ys[tm * 4 + j][k];
#pragma unroll
        for (int i = 0; i < 4; i++)
#pragma unroll
            for (int j = 0; j < 4; j++) acc[i][j] += a[i] * bb_[j];
    }

    const float negScale = -g_inv_eps * LOG2E;
    float tmin = INFINITY;
#pragma unroll
    for (int i = 0; i < 4; i++) {
        int n = n0 + tn * 4 + i;
        float xx = g_x2[b * NN + n];
        float4 cv;
        float c[4];
#pragma unroll
        for (int j = 0; j < 4; j++) {
            int m = m0 + tm * 4 + j;
            float v = xx + g_y2[b * NN + m] - 2.0f * acc[i][j];
            v = fmaxf(v, 0.0f);
            tmin = fminf(tmin, v);
            c[j] = v * negScale;
        }
        cv.x = c[0]; cv.y = c[1]; cv.z = c[2]; cv.w = c[3];
        *(float4*)(g_C + ((size_t)(b * NN + n)) * NN + m0 + tm * 4) = cv;
    }

#pragma unroll
    for (int off = 16; off > 0; off >>= 1)
        tmin = fminf(tmin, __shfl_xor_sync(0xFFFFFFFFu, tmin, off));
    if ((t & 31) == 0) wmin[t >> 5] = tmin;
    __syncthreads();
    if (t == 0) {
        float bm = wmin[0];
#pragma unroll
        for (int w = 1; w < 8; w++) bm = fminf(bm, wmin[w]);
        atomicMin(&g_cminbits[b], __float_as_uint(bm));
    }
}

// ---------------- init Lu2/Lv2 = cmin*inv_eps*LOG2E (log_u = log_v = 0) -----
__global__ void k_init() {
    int idx = blockIdx.x * blockDim.x + threadIdx.x;
    if (idx < BB * NN) {
        int b = idx >> 10;
        float cminv2 = __uint_as_float(g_cminbits[b]) * g_inv_eps * LOG2E;
        g_Lu2[idx] = cminv2;
        g_Lv2[idx] = cminv2;
    }
}

// ---------------- initial column pass (run once): tile partial sums ----------
// Block = (64 cols) x (64-row slab) x batch. 256 threads = 16 colgroups x
// 16 rowparts of 4 rows.
__global__ void __launch_bounds__(256) k_colP() {
    __shared__ float lus[64];
    __shared__ float4 part[16][16];   // [rowpart p][colgroup g]

    const int b    = blockIdx.z;
    const int m0   = blockIdx.x * 64;
    const int slab = blockIdx.y;
    const int n0   = slab * 64;
    const int t    = threadIdx.x;
    const int g    = t & 15;
    const int p    = t >> 4;

    if (t < 64) lus[t] = g_Lu2[b * NN + n0 + t];

    const float cminv2 = __uint_as_float(g_cminbits[b]) * g_inv_eps * LOG2E;
    const float Cv = cminv2 - 10.0f;   // - log2(1024)

    float4 pl = *(const float4*)(g_Lv2 + b * NN + m0 + 4 * g);
    float4 V0;
    V0.x = Cv - pl.x; V0.y = Cv - pl.y; V0.z = Cv - pl.z; V0.w = Cv - pl.w;
    __syncthreads();

    const float4* Cp = (const float4*)(g_C + ((size_t)(b * NN + n0)) * NN) + (m0 >> 2) + g;
    float s0 = 0.f, s1 = 0.f, s2 = 0.f, s3 = 0.f;
#pragma unroll
    for (int n = 4 * p; n < 4 * p + 4; n++) {
        float4 c = Cp[(size_t)n * (NN / 4)];
        float lu = lus[n];
        s0 += ex2(c.x + lu - V0.x);
        s1 += ex2(c.y + lu - V0.y);
        s2 += ex2(c.z + lu - V0.z);
        s3 += ex2(c.w + lu - V0.w);
    }
    part[p][g] = make_float4(s0, s1, s2, s3);
    __syncthreads();

    if (t < 64) {
        int gg = t >> 2, j = t & 3;
        float s = 0.0f;
#pragma unroll
        for (int q = 0; q < 16; q++) s += ((const float*)&part[q][gg])[j];
        g_part[((size_t)(b * NPART + slab)) * NN + m0 + t] = s;
    }
}

// ---------------- combine partials + log -> Lv2 ------------------------------
// grid (4, BB) x 256 threads; thread = one column; coalesced partial loads.
__global__ void __launch_bounds__(256) k_finv() {
    const int b = blockIdx.y;
    const int m = blockIdx.x * 256 + threadIdx.x;

    const float cminv2 = __uint_as_float(g_cminbits[b]) * g_inv_eps * LOG2E;
    const float Cv = cminv2 - 10.0f;

    const float* P = g_part + (size_t)b * NPART * NN + m;
    float s = 0.0f;
#pragma unroll
    for (int p = 0; p < NPART; p++) s += P[p * NN];

    float V = Cv - g_Lv2[b * NN + m];   // old V0 used by the partial pass
    float LSE2 = V + lg2(fmaxf(s, 1e-38f));
    g_Lv2[b * NN + m] = Cv - LSE2;
}

// ---------------- fused pass: u-update + column partials for next v ----------
// Block = 64 rows of one batch; 8 warps x 8 rows; warp owns the whole row,
// no intra-loop syncs. Grid = NPART*BB = 256 blocks -> exactly ONE wave at
// 2 blocks/SM residency (vs 512 blocks = 1.73 ragged waves before).
// ONE read of C serves both updates:
//   e[m] = exp2(C2 + Lv[m] - V0r);  Lu_new = Cc - (V0r + log2(sum_m e));
//   column contribution = e[m] * exp2(Lu_new - Lu_old)   (exact identity).
__global__ void __launch_bounds__(256, 2) k_fused() {
    __shared__ float4 lv2s[NN / 4];     // 4 KB
    __shared__ float swacc[8][NN];      // 32 KB per-warp column partials

    const int b    = blockIdx.y;
    const int t    = threadIdx.x;
    const int lane = t & 31;
    const int w    = t >> 5;
    const int r0   = blockIdx.x * 64 + w * 8;

    lv2s[t] = ((const float4*)(g_Lv2 + b * NN))[t];

    const float cminv2 = __uint_as_float(g_cminbits[b]) * g_inv_eps * LOG2E;
    const float Cc = cminv2 - 10.0f;
    __syncthreads();

    float4 colacc[8];
#pragma unroll
    for (int j = 0; j < 8; j++) colacc[j] = make_float4(0.f, 0.f, 0.f, 0.f);

#pragma unroll 2
    for (int rr = 0; rr < 8; rr++) {
        const int row = r0 + rr;
        const float Lu_old = g_Lu2[b * NN + row];
        const float V0 = Cc - Lu_old;
        const float4* Crow = (const float4*)(g_C + ((size_t)(b * NN + row)) * NN);

        float4 e[8];
        float s0 = 0.f, s1 = 0.f, s2 = 0.f, s3 = 0.f;
#pragma unroll
        for (int j = 0; j < 8; j++) {
            int i = lane + 32 * j;
            float4 c = Crow[i];
            float4 lv = lv2s[i];
            e[j].x = ex2(c.x + lv.x - V0);
            e[j].y = ex2(c.y + lv.y - V0);
            e[j].z = ex2(c.z + lv.z - V0);
            e[j].w = ex2(c.w + lv.w - V0);
            s0 += e[j].x; s1 += e[j].y; s2 += e[j].z; s3 += e[j].w;
        }
        float s = (s0 + s1) + (s2 + s3);
#pragma unroll
        for (int off = 16; off > 0; off >>= 1)
            s += __shfl_xor_sync(0xFFFFFFFFu, s, off);

        float LSE2 = V0 + lg2(fmaxf(s, 1e-38f));
        float Lu_new = Cc - LSE2;
        if (lane == 0) g_Lu2[b * NN + row] = Lu_new;

        float An = ex2(Lu_new - Lu_old);
#pragma unroll
        for (int j = 0; j < 8; j++) {
            colacc[j].x += e[j].x * An;
            colacc[j].y += e[j].y * An;
            colacc[j].z += e[j].z * An;
            colacc[j].w += e[j].w * An;
        }
    }

    // dump per-warp accumulators to smem
#pragma unroll
    for (int j = 0; j < 8; j++)
        ((float4*)swacc[w])[lane + 32 * j] = colacc[j];
    __syncthreads();

    // combine 8 warps -> one partial per block (conflict-free: consecutive m)
    float* dst = g_part + ((size_t)(b * NPART + blockIdx.x)) * NN;
#pragma unroll
    for (int q = 0; q < 4; q++) {
        int m = t + 256 * q;
        float s = 0.f;
#pragma unroll
        for (int ww = 0; ww < 8; ww++) s += swacc[ww][m];
        dst[m] = s;
    }
}

// ---------------- output -----------------------------------------------------
// w[n,m] = exp2(C2[n,m] + Lu2[n] + Lv2[m] - cminv2); out = (w @ y) / rowsum(w)
__global__ void k_out(const float* __restrict__ y, float* __restrict__ out) {
    __shared__ __align__(16) float ysm[64 * 64];
    __shared__ float wt[16 * 65];

    const int b  = blockIdx.y;
    const int n0 = blockIdx.x * 16;
    const int t  = threadIdx.x;
    const int r  = t >> 4;
    const int dg = t & 15;

    const float cminv2 = __uint_as_float(g_cminbits[b]) * g_inv_eps * LOG2E;

    float4 acc = make_float4(0.f, 0.f, 0.f, 0.f);
    float wsum = 0.0f;

    for (int mt = 0; mt < NN; mt += 64) {
#pragma unroll
        for (int r2 = 0; r2 < 4; r2++) {
            int fid = t + 256 * r2;
            int row = fid >> 4;
            int col4 = fid & 15;
            ((float4*)ysm)[fid] =
                *(const float4*)(y + ((size_t)(b * NN + mt + row)) * DD + col4 * 4);
        }
        {
            int wid = t * 4;
            int rw = wid >> 6;
            int mmw = wid & 63;
            float4 cv = *(const float4*)(g_C + ((size_t)(b * NN + n0 + rw)) * NN + mt + mmw);
            float4 lv = *(const float4*)(g_Lv2 + b * NN + mt + mmw);
            float lu = g_Lu2[b * NN + n0 + rw] - cminv2;
            wt[rw * 65 + mmw + 0] = ex2(cv.x + lv.x + lu);
            wt[rw * 65 + mmw + 1] = ex2(cv.y + lv.y + lu);
            wt[rw * 65 + mmw + 2] = ex2(cv.z + lv.z + lu);
            wt[rw * 65 + mmw + 3] = ex2(cv.w + lv.w + lu);
        }
        __syncthreads();

#pragma unroll 16
        for (int mm = 0; mm < 64; mm++) {
            float w = wt[r * 65 + mm];
            float4 yv = *(const float4*)(ysm + mm * 64 + dg * 4);
            acc.x += w * yv.x;
            acc.y += w * yv.y;
            acc.z += w * yv.z;
            acc.w += w * yv.w;
            wsum += w;
        }
        __syncthreads();
    }

    float rinv = 1.0f / fmaxf(wsum, 1e-12f);
    float4 o;
    o.x = acc.x * rinv; o.y = acc.y * rinv;
    o.z = acc.z * rinv; o.w = acc.w * rinv;
    *(float4*)(out + ((size_t)(b * NN + n0 + r)) * DD + dg * 4) = o;
}

// ---------------- launcher ---------------------------------------------------
extern "C" void kernel_launch(void* const* d_in, const int* in_sizes, int n_in,
                              void* d_out, int out_size) {
    const float* x = (const float*)d_in[0];
    const float* y = (const float*)d_in[1];
    const void* eps = d_in[2];
    float* out = (float*)d_out;

    k_prep<<<(2 * BB * NN + 255) / 256, 256>>>(x, y, eps);
    k_gemm<<<dim3(NN / 64, NN / 64, BB), 256>>>(x, y);
    k_init<<<(BB * NN + 255) / 256, 256>>>();

    // v-update #1 (uses Lu = init)
    k_colP<<<dim3(NN / 64, NPART, BB), 256>>>();
    k_finv<<<dim3(NN / 256, BB), 256>>>();

    // 50 x { u-update k ; column partials for v-update k+1 ; finish v-update }
    for (int it = 0; it < 50; it++) {
        k_fused<<<dim3(NPART, BB), 256>>>();
        k_finv<<<dim3(NN / 256, BB), 256>>>();
    }

    k_out<<<dim3(NN / 16, BB), 256>>>(y, out);
}